// round 3
// baseline (speedup 1.0000x reference)
#include <cuda_runtime.h>
#include <cuda_bf16.h>
#include <cstdint>

// Problem constants (fixed by the reference setup_inputs).
constexpr int B  = 4096;
constexpr int D  = 784;
constexpr int O1 = 8192;
constexpr int O2 = 8192;
constexpr int OT = O1 + O2;

constexpr int RG       = 8;          // row-groups per block (each float4 = 4 rows)
constexpr int ROWS_PB  = RG * 4;     // 32 rows per block
constexpr int STRIDE   = 785;        // odd float4 stride -> conflict-free LDS.128
constexpr int NTHREADS = 512;
constexpr int NWARPS   = NTHREADS / 32;
constexpr int SMEM_BYTES = RG * STRIDE * (int)sizeof(float4);  // 100480 B

__device__ __forceinline__ float4 mul4(float4 a, float4 b) {
    return make_float4(a.x * b.x, a.y * b.y, a.z * b.z, a.w * b.w);
}
__device__ __forceinline__ float getc(const float4& v, int c) {
    return reinterpret_cast<const float*>(&v)[c];  // c is unroll-constant
}

__global__ __launch_bounds__(NTHREADS)
void random_de_kernel(const float* __restrict__ x,
                      const int*   __restrict__ idx1,
                      const int*   __restrict__ idx2,
                      float*       __restrict__ out)
{
    extern __shared__ float4 xs[];   // logically [RG][STRIDE]

    const int row0 = blockIdx.x * ROWS_PB;
    const int tid  = threadIdx.x;

    // ---- Stage 32 rows into xs[rg][d] with rows in float4 components ----
    for (int i = tid; i < ROWS_PB * (D / 4); i += NTHREADS) {
        const int r  = i / (D / 4);
        const int dq = i % (D / 4);
        const float4 v = reinterpret_cast<const float4*>(
            x + (size_t)(row0 + r) * D)[dq];
        const int rg = r >> 2, c = r & 3;
        float* base = reinterpret_cast<float*>(xs) +
                      ((size_t)rg * STRIDE + dq * 4) * 4 + c;
        base[0]  = v.x;
        base[4]  = v.y;
        base[8]  = v.z;
        base[12] = v.w;
    }
    __syncthreads();

    const int warp  = tid >> 5;
    const int lane  = tid & 31;
    const int o_sub = lane >> 3;      // which of 4 outputs in the quad
    const int rg    = lane & 7;       // which row-group
    const float4* __restrict__ xrow = xs + (size_t)rg * STRIDE;

    // ---- Pairs: outputs [0, O1). Tiles of 16 outputs per warp-iter. ----
    {
        const int2* __restrict__ idx1v = reinterpret_cast<const int2*>(idx1);
        for (int tile = warp; tile < O1 / 16; tile += NWARPS) {
            const int o0 = tile * 16 + o_sub * 4;
            float4 v[4];
            #pragma unroll
            for (int i = 0; i < 4; i++) {
                const int2 p = __ldg(&idx1v[o0 + i]);
                v[i] = mul4(xrow[p.x], xrow[p.y]);   // conflict-free LDS.128
            }
            #pragma unroll
            for (int c = 0; c < 4; c++) {
                const int row = row0 + rg * 4 + c;
                *reinterpret_cast<float4*>(out + (size_t)row * OT + o0) =
                    make_float4(getc(v[0], c), getc(v[1], c),
                                getc(v[2], c), getc(v[3], c));
            }
        }
    }

    // ---- Triples: outputs [O1, OT). ----
    {
        for (int tile = warp; tile < O2 / 16; tile += NWARPS) {
            const int o0 = tile * 16 + o_sub * 4;
            float4 v[4];
            #pragma unroll
            for (int i = 0; i < 4; i++) {
                const int o = o0 + i;
                const int ia = __ldg(idx2 + (size_t)o * 3 + 0);
                const int ib = __ldg(idx2 + (size_t)o * 3 + 1);
                const int ic = __ldg(idx2 + (size_t)o * 3 + 2);
                v[i] = mul4(mul4(xrow[ia], xrow[ib]), xrow[ic]);
            }
            #pragma unroll
            for (int c = 0; c < 4; c++) {
                const int row = row0 + rg * 4 + c;
                *reinterpret_cast<float4*>(out + (size_t)row * OT + O1 + o0) =
                    make_float4(getc(v[0], c), getc(v[1], c),
                                getc(v[2], c), getc(v[3], c));
            }
        }
    }
}

extern "C" void kernel_launch(void* const* d_in, const int* in_sizes, int n_in,
                              void* d_out, int out_size)
{
    const float* x    = (const float*)d_in[0];
    const int*   idx1 = (const int*)d_in[1];
    const int*   idx2 = (const int*)d_in[2];
    float*       out  = (float*)d_out;

    // Non-stream API: executes immediately, capture-safe, idempotent.
    cudaFuncSetAttribute(random_de_kernel,
                         cudaFuncAttributeMaxDynamicSharedMemorySize,
                         SMEM_BYTES);

    dim3 grid(B / ROWS_PB);  // 128 blocks
    random_de_kernel<<<grid, NTHREADS, SMEM_BYTES>>>(x, idx1, idx2, out);
}